// round 7
// baseline (speedup 1.0000x reference)
#include <cuda_runtime.h>
#include <cuda_fp16.h>
#include <cstdint>

// Problem constants
#define BDIM  256          // B = BATCH*NBR
#define LDIM  64
#define DIN   64           // 2*K*U
#define HDIM  512
#define CDIM  1024         // 2*h
#define MOUT  144
#define BL    16384        // B*L
#define NS_STRIDE ((size_t)BL * HDIM)
#define OUT_FRE  0
#define OUT_FIM  524288
#define OUT_I    1048576

// ---------------- scratch ----------------
__device__ __align__(128) __half g_A0h[BDIM * LDIM * DIN];   // 2 MB
__device__ __align__(128) __half g_A0l[BDIM * LDIM * DIN];   // 2 MB
__device__ __align__(128) float g_Y [LDIM * BDIM * CDIM];    // 64 MB [n][b][o]
__device__ __align__(128) __half g_Mh[BL * HDIM];            // 16 MB [(b*64+n)][h]
__device__ __align__(128) __half g_Ml[BL * HDIM];            // 16 MB
__device__ __align__(128) float g_Y2[LDIM * BDIM * MOUT];    //  9 MB [n][b][c]
__device__ float g_pS [256 * CDIM];
__device__ float g_pS2[256 * CDIM];
__device__ float g_scale[CDIM];
__device__ float g_shift[CDIM];
__device__ float g_Ipart[BL];

// ================= helpers =================
__device__ __forceinline__ uint32_t smem_u32(const void* p) {
    uint32_t a;
    asm("{ .reg .u64 t; cvta.to.shared.u64 t, %1; cvt.u32.u64 %0, t; }" : "=r"(a) : "l"(p));
    return a;
}
__device__ __forceinline__ void ldmx4(uint32_t* r, uint32_t addr) {
    asm volatile("ldmatrix.sync.aligned.m8n8.x4.shared.b16 {%0,%1,%2,%3}, [%4];"
        : "=r"(r[0]), "=r"(r[1]), "=r"(r[2]), "=r"(r[3]) : "r"(addr));
}
__device__ __forceinline__ void mma_f16(float* c, const uint32_t* a,
                                        uint32_t b0, uint32_t b1) {
    asm volatile("mma.sync.aligned.m16n8k16.row.col.f32.f16.f16.f32 "
        "{%0,%1,%2,%3}, {%4,%5,%6,%7}, {%8,%9}, {%0,%1,%2,%3};"
        : "+f"(c[0]), "+f"(c[1]), "+f"(c[2]), "+f"(c[3])
        : "r"(a[0]), "r"(a[1]), "r"(a[2]), "r"(a[3]), "r"(b0), "r"(b1));
}
#define CP_ASYNC16(dst, src) \
    asm volatile("cp.async.ca.shared.global [%0], [%1], 16;" :: "r"(dst), "l"(src))
#define CP_COMMIT() asm volatile("cp.async.commit_group;")
#define CP_WAIT0()  asm volatile("cp.async.wait_group 0;")

// fp32x4 -> fp16 hi + fp16 residual lo (packed)
__device__ __forceinline__ void cvt_hilo_h(float4 v, uint2& hi, uint2& lo) {
    __half2 h01 = __floats2half2_rn(v.x, v.y);
    __half2 h23 = __floats2half2_rn(v.z, v.w);
    float2 f01 = __half22float2(h01);
    float2 f23 = __half22float2(h23);
    __half2 l01 = __floats2half2_rn(v.x - f01.x, v.y - f01.y);
    __half2 l23 = __floats2half2_rn(v.z - f23.x, v.w - f23.y);
    hi.x = *reinterpret_cast<uint32_t*>(&h01);
    hi.y = *reinterpret_cast<uint32_t*>(&h23);
    lo.x = *reinterpret_cast<uint32_t*>(&l01);
    lo.y = *reinterpret_cast<uint32_t*>(&l23);
}

// ================= tensor-core batched GEMM =================
// fp16 3-term: Ph*Ah + Ph*Al + Pl*Ah  (drops only Pl*Al ~ 2^-22)
// Y[n][b][o] = sum_d P[n][o][d] * Act[(b*64+n)][d]
// CTA tile 128b x 128o x 64k; 8 warps (2b x 4o), warp tile 64x32.
// smem buffer: AH 16K | AL 16K | PH 16K | PL 16K ; double buffered (128 KB).
#define GBUF 65536
#define GSMEM (2 * GBUF)

__global__ __launch_bounds__(256) void gemm_mma(
    const float* __restrict__ Pw,
    const __half* __restrict__ Ah, const __half* __restrict__ Al,
    float* __restrict__ Y, int K, int M, int relu, int stats)
{
    extern __shared__ char sm[];
    const int tid = threadIdx.x, wid = tid >> 5, lid = tid & 31;
    const int m0 = blockIdx.x * 128, b0 = blockIdx.y * 128, n = blockIdx.z;
    const int nchunk = K >> 6;
    uint32_t sb = smem_u32(sm);

    // global-load indexing
    const int r0 = tid >> 4, c4 = tid & 15;
    const int cswP = (((c4 >> 1) ^ (r0 & 7)) << 4) + (c4 & 1) * 8;
    const int ac = c4 & 7;
    const int aregion = (c4 < 8) ? 0 : 16384;
    const int cswA = ((ac ^ (r0 & 7)) << 4);
    const __half* Asrc = (c4 < 8) ? Ah : Al;

    // ldmatrix lane geometry
    const int lr  = (lid & 7) + ((lid >> 3) & 1) * 8;
    const int kch = lid >> 4;
    const int warp_b = wid >> 2, warp_o = wid & 3;
    int rowA128[4], r7A[4], rowB128[2], r7B[2];
#pragma unroll
    for (int mm = 0; mm < 4; mm++) {
        int r = warp_b * 64 + mm * 16 + lr;
        rowA128[mm] = r * 128; r7A[mm] = r & 7;
    }
#pragma unroll
    for (int g = 0; g < 2; g++) {
        int r = warp_o * 32 + g * 16 + lr;
        rowB128[g] = r * 128; r7B[g] = r & 7;
    }

    float acc[4][4][4];
#pragma unroll
    for (int i = 0; i < 4; i++)
#pragma unroll
        for (int j = 0; j < 4; j++)
#pragma unroll
            for (int q = 0; q < 4; q++) acc[i][j][q] = 0.f;

    float4 stP[8];

    // ---- prologue: chunk 0 ----
#pragma unroll
    for (int j = 0; j < 8; j++) {
        int row = j * 16 + r0;
        const void* src = &Asrc[((size_t)(b0 + row) * 64 + n) * K + ac * 8];
        CP_ASYNC16(sb + aregion + row * 128 + cswA, src);
    }
    CP_COMMIT();
#pragma unroll
    for (int j = 0; j < 8; j++) {
        int row = j * 16 + r0;
        if (m0 + row < M)
            stP[j] = *(const float4*)&Pw[((size_t)n * M + m0 + row) * K + c4 * 4];
        else stP[j] = make_float4(0.f, 0.f, 0.f, 0.f);
    }
#pragma unroll
    for (int j = 0; j < 8; j++) {
        int row = j * 16 + r0;
        uint2 hi, lo;
        cvt_hilo_h(stP[j], hi, lo);
        *(uint2*)(sm + 32768 + row * 128 + cswP) = hi;
        *(uint2*)(sm + 49152 + row * 128 + cswP) = lo;
    }
    CP_WAIT0();
    __syncthreads();

    for (int c = 0; c < nchunk; c++) {
        if (c + 1 < nchunk) {
            int k0 = (c + 1) << 6;
            uint32_t bdst = sb + ((c + 1) & 1) * GBUF;
#pragma unroll
            for (int j = 0; j < 8; j++) {
                int row = j * 16 + r0;
                const void* src = &Asrc[((size_t)(b0 + row) * 64 + n) * K + k0 + ac * 8];
                CP_ASYNC16(bdst + aregion + row * 128 + cswA, src);
            }
            CP_COMMIT();
#pragma unroll
            for (int j = 0; j < 8; j++) {
                int row = j * 16 + r0;
                if (m0 + row < M)
                    stP[j] = *(const float4*)&Pw[((size_t)n * M + m0 + row) * K + k0 + c4 * 4];
                else stP[j] = make_float4(0.f, 0.f, 0.f, 0.f);
            }
        }

        // ---- compute on buffer c&1 ----
        uint32_t ub = sb + (c & 1) * GBUF;
#pragma unroll
        for (int kk = 0; kk < 4; kk++) {
            uint32_t ah[4][4], al[4][4], bh[2][4], bl2[2][4];
            int ksel = kk * 2 + kch;
#pragma unroll
            for (int mm = 0; mm < 4; mm++)
                ldmx4(ah[mm], ub + rowA128[mm] + ((ksel ^ r7A[mm]) << 4));
#pragma unroll
            for (int mm = 0; mm < 4; mm++)
                ldmx4(al[mm], ub + 16384 + rowA128[mm] + ((ksel ^ r7A[mm]) << 4));
#pragma unroll
            for (int g = 0; g < 2; g++)
                ldmx4(bh[g], ub + 32768 + rowB128[g] + ((ksel ^ r7B[g]) << 4));
#pragma unroll
            for (int g = 0; g < 2; g++)
                ldmx4(bl2[g], ub + 49152 + rowB128[g] + ((ksel ^ r7B[g]) << 4));
#pragma unroll
            for (int mm = 0; mm < 4; mm++)
#pragma unroll
                for (int nn = 0; nn < 4; nn++) {
                    int g = nn >> 1, s = nn & 1;
                    mma_f16(acc[mm][nn], ah[mm], bh[g][s],  bh[g][s + 2]);
                    mma_f16(acc[mm][nn], al[mm], bh[g][s],  bh[g][s + 2]);
                    mma_f16(acc[mm][nn], ah[mm], bl2[g][s], bl2[g][s + 2]);
                }
        }

        if (c + 1 < nchunk) {
            char* buf = sm + ((c + 1) & 1) * GBUF;
#pragma unroll
            for (int j = 0; j < 8; j++) {
                int row = j * 16 + r0;
                uint2 hi, lo;
                cvt_hilo_h(stP[j], hi, lo);
                *(uint2*)(buf + 32768 + row * 128 + cswP) = hi;
                *(uint2*)(buf + 49152 + row * 128 + cswP) = lo;
            }
            CP_WAIT0();
        }
        __syncthreads();
    }

    // ---- epilogue ----
    if (relu) {
#pragma unroll
        for (int i = 0; i < 4; i++)
#pragma unroll
            for (int j = 0; j < 4; j++)
#pragma unroll
                for (int q = 0; q < 4; q++) acc[i][j][q] = fmaxf(acc[i][j][q], 0.f);
    }

#pragma unroll
    for (int mm = 0; mm < 4; mm++) {
        int bg = b0 + warp_b * 64 + mm * 16 + (lid >> 2);
#pragma unroll
        for (int nn = 0; nn < 4; nn++) {
            int og = m0 + warp_o * 32 + nn * 8 + (lid & 3) * 2;
            if (og < M) {
                float2 v01 = make_float2(acc[mm][nn][0], acc[mm][nn][1]);
                float2 v23 = make_float2(acc[mm][nn][2], acc[mm][nn][3]);
                *(float2*)&Y[((size_t)n * 256 + bg) * M + og] = v01;
                *(float2*)&Y[((size_t)n * 256 + bg + 8) * M + og] = v23;
            }
        }
    }

    // fused BN partial stats (deterministic per-slot, no atomics)
    if (stats) {
        float s1[8], s2v[8];
#pragma unroll
        for (int k = 0; k < 8; k++) { s1[k] = 0.f; s2v[k] = 0.f; }
#pragma unroll
        for (int nn = 0; nn < 4; nn++)
#pragma unroll
            for (int q = 0; q < 2; q++) {
                int k = nn * 2 + q;
#pragma unroll
                for (int mm = 0; mm < 4; mm++) {
                    float v0 = acc[mm][nn][q], v1 = acc[mm][nn][q + 2];
                    s1[k] += v0 + v1;
                    s2v[k] += v0 * v0 + v1 * v1;
                }
            }
#pragma unroll
        for (int k = 0; k < 8; k++)
#pragma unroll
            for (int msk = 4; msk <= 16; msk <<= 1) {
                s1[k]  += __shfl_xor_sync(0xFFFFFFFFu, s1[k],  msk);
                s2v[k] += __shfl_xor_sync(0xFFFFFFFFu, s2v[k], msk);
            }
        if ((lid >> 2) == 0) {
            int slot = (blockIdx.y * 64 + blockIdx.z) * 2 + warp_b;
#pragma unroll
            for (int nn = 0; nn < 4; nn++)
#pragma unroll
                for (int q = 0; q < 2; q++) {
                    int ch = m0 + warp_o * 32 + nn * 8 + (lid & 3) * 2 + q;
                    g_pS [slot * CDIM + ch] = s1[nn * 2 + q];
                    g_pS2[slot * CDIM + ch] = s2v[nn * 2 + q];
                }
        }
    }
}

// ================= pre/post kernels =================
__global__ void build_a0(const float* __restrict__ Hre, const float* __restrict__ Him) {
    int b = blockIdx.x, t = threadIdx.x;
    const float* hr = Hre + (size_t)b * 2048;
    const float* hi = Him + (size_t)b * 2048;
    size_t dbase = (size_t)b * 4096;
#pragma unroll
    for (int j = 0; j < 8; j++) {
        int idx = t + j * 256;
        int n = idx >> 5, d = idx & 31;
        float v0 = hr[idx], v1 = hi[idx];
        __half h0 = __float2half_rn(v0);
        __half h1 = __float2half_rn(v1);
        g_A0h[dbase + n * 64 + d]      = h0;
        g_A0h[dbase + n * 64 + 32 + d] = h1;
        g_A0l[dbase + n * 64 + d]      = __float2half_rn(v0 - __half2float(h0));
        g_A0l[dbase + n * 64 + 32 + d] = __float2half_rn(v1 - __half2float(h1));
    }
}

__global__ void bn_finalize(const float* __restrict__ w, const float* __restrict__ bb) {
    int o = blockIdx.x * 128 + threadIdx.x;
    float s = 0.f, s2 = 0.f;
#pragma unroll 8
    for (int sl = 0; sl < 256; sl++) {
        s  += g_pS [sl * CDIM + o];
        s2 += g_pS2[sl * CDIM + o];
    }
    float mean = s / (float)BL;
    float var  = s2 / (float)BL - mean * mean;
    float sc = w[o] * rsqrtf(var + 1e-5f);
    g_scale[o] = sc;
    g_shift[o] = bb[o] - mean * sc;
}

// fused BN-apply + softplus + closed-form noise MI
// 256 threads, 2 rows (nb) per block; each half-block covers 512 cols via float4
__global__ void bn_noise(const float* __restrict__ Y, const float* __restrict__ Nz, int add) {
    int t = threadIdx.x;
    int sub = t >> 7, tt = t & 127;
    int nb = blockIdx.x * 2 + sub;
    int n = nb >> 8, b = nb & 255;
    size_t ybase = (size_t)nb * CDIM;
    size_t bl = (size_t)b * 64 + n;
    size_t mbase = bl * HDIM;
    int d = tt * 4;

    float4 ym = *(const float4*)&Y[ybase + d];
    float4 ys = *(const float4*)&Y[ybase + HDIM + d];
    float4 scm = *(const float4*)&g_scale[d];
    float4 shm = *(const float4*)&g_shift[d];
    float4 scs = *(const float4*)&g_scale[HDIM + d];
    float4 shs = *(const float4*)&g_shift[HDIM + d];
    float4 n0 = *(const float4*)&Nz[mbase + d];
    float4 n1 = *(const float4*)&Nz[mbase + d + NS_STRIDE];
    float4 n2 = *(const float4*)&Nz[mbase + d + 2 * NS_STRIDE];
    float4 n3 = *(const float4*)&Nz[mbase + d + 3 * NS_STRIDE];

    float m[4] = { scm.x * ym.x + shm.x, scm.y * ym.y + shm.y,
                   scm.z * ym.z + shm.z, scm.w * ym.w + shm.w };
    float x[4] = { scs.x * ys.x + shs.x, scs.y * ys.y + shs.y,
                   scs.z * ys.z + shs.z, scs.w * ys.w + shs.w };
    float nn0[4] = { n0.x, n0.y, n0.z, n0.w };
    float nn1[4] = { n1.x, n1.y, n1.z, n1.w };
    float nn2[4] = { n2.x, n2.y, n2.z, n2.w };
    float nn3[4] = { n3.x, n3.y, n3.z, n3.w };

    float local = 0.f;
    float lo[4];
#pragma unroll
    for (int i = 0; i < 4; i++) {
        float s = fmaxf(x[i], 0.f) + log1pf(__expf(-fabsf(x[i]))) + 1e-10f;
        float S1 = (nn0[i] + nn1[i] + nn2[i] + nn3[i]) * 0.25f;
        float S2 = (nn0[i] * nn0[i] + nn1[i] * nn1[i] +
                    nn2[i] * nn2[i] + nn3[i] * nn3[i]) * 0.25f;
        local += 0.5f * m[i] * m[i] - __logf(s) + m[i] * s * S1
               + 0.5f * (s * s - 1.0f) * S2;
        __half mh = __float2half_rn(m[i]);
        lo[i] = m[i] - __half2float(mh);
        m[i] = __half2float(mh);
    }
    __half2 mh01 = __floats2half2_rn(m[0], m[1]);
    __half2 mh23 = __floats2half2_rn(m[2], m[3]);
    __half2 ml01 = __floats2half2_rn(lo[0], lo[1]);
    __half2 ml23 = __floats2half2_rn(lo[2], lo[3]);
    uint2 hv, lv;
    hv.x = *reinterpret_cast<uint32_t*>(&mh01);
    hv.y = *reinterpret_cast<uint32_t*>(&mh23);
    lv.x = *reinterpret_cast<uint32_t*>(&ml01);
    lv.y = *reinterpret_cast<uint32_t*>(&ml23);
    *(uint2*)&g_Mh[mbase + d] = hv;
    *(uint2*)&g_Ml[mbase + d] = lv;

    __shared__ float sh[256];
    sh[t] = local;
    __syncthreads();
    for (int off = 64; off; off >>= 1) {
        if (tt < off) sh[t] += sh[t + off];
        __syncthreads();
    }
    if (tt == 0) {
        if (add) g_Ipart[bl] += sh[t];
        else     g_Ipart[bl]  = sh[t];
    }
}

// merged pn + final + I-sum: one block per b (256 blocks, 128 threads)
__global__ void epilogue_kernel(float* __restrict__ out) {
    int b = blockIdx.x, t = threadIdx.x;
    __shared__ float v[64][72];
    __shared__ float pk[64];
    __shared__ float Pn[8];
    __shared__ float mult[64][8];

    for (int idx = t; idx < 64 * 72; idx += 128) {
        int n = idx / 72, c = idx % 72;
        v[n][c] = g_Y2[((size_t)(n * 256 + b)) * MOUT + c];
    }
    __syncthreads();
    if (t < 64) {
        int k = t & 7, j = t >> 3;
        float s = 0.f;
#pragma unroll
        for (int n = j; n < 64; n += 8) { float x = v[n][64 + k]; s += x * x; }
        pk[t] = s;
    }
    __syncthreads();
    if (t < 8) {
        float tot = 0.f;
#pragma unroll
        for (int j = 0; j < 8; j++) tot += pk[j * 8 + t];
        Pn[t] = sqrtf(tot);
    }
    __syncthreads();
    for (int idx = t; idx < 512; idx += 128) {
        int n = idx >> 3, k = idx & 7;
        float ss = 0.f;
#pragma unroll
        for (int u = 0; u < 4; u++) {
            float a = v[n][k * 4 + u], c2 = v[n][32 + k * 4 + u];
            ss += a * a + c2 * c2;
        }
        mult[n][k] = v[n][64 + k] / Pn[k] * 8.0f / sqrtf(ss);  // sqrt(L)=8
    }
    __syncthreads();
    for (int idx = t; idx < 64 * 32; idx += 128) {
        int n = idx >> 5, c = idx & 31;
        size_t obase = ((size_t)b * 64 + n) * 32;
        float mlt = mult[n][c >> 2];
        out[OUT_FRE + obase + c] = v[n][c] * mlt;
        out[OUT_FIM + obase + c] = v[n][32 + c] * mlt;
    }
    if (t < 64) pk[t] = g_Ipart[(size_t)b * 64 + t];
    __syncthreads();
    if (t == 0) {
        float s = 0.f;
#pragma unroll
        for (int n = 0; n < 64; n++) s += pk[n];
        out[OUT_I + b] = s;
    }
}

// ================= launch =================
extern "C" void kernel_launch(void* const* d_in, const int* in_sizes, int n_in,
                              void* d_out, int out_size) {
    const float* Hre = (const float*)d_in[0];
    const float* Him = (const float*)d_in[1];
    const float* P0  = (const float*)d_in[2];
    const float* P1  = (const float*)d_in[3];
    const float* P2  = (const float*)d_in[4];
    const float* w0  = (const float*)d_in[5];
    const float* b0  = (const float*)d_in[6];
    const float* w1  = (const float*)d_in[7];
    const float* b1  = (const float*)d_in[8];
    const float* nz0 = (const float*)d_in[9];
    const float* nz1 = (const float*)d_in[10];
    float* out = (float*)d_out;

    float *Yp, *Y2p;
    __half *A0h, *A0l, *Mh, *Ml;
    cudaGetSymbolAddress((void**)&A0h, g_A0h);
    cudaGetSymbolAddress((void**)&A0l, g_A0l);
    cudaGetSymbolAddress((void**)&Yp,  g_Y);
    cudaGetSymbolAddress((void**)&Mh,  g_Mh);
    cudaGetSymbolAddress((void**)&Ml,  g_Ml);
    cudaGetSymbolAddress((void**)&Y2p, g_Y2);

    cudaFuncSetAttribute(gemm_mma, cudaFuncAttributeMaxDynamicSharedMemorySize, GSMEM);

    // layer 0: K=64
    build_a0<<<BDIM, 256>>>(Hre, Him);
    gemm_mma<<<dim3(8, 2, 64), 256, GSMEM>>>(P0, A0h, A0l, Yp, DIN, CDIM, 1, 1);
    bn_finalize<<<8, 128>>>(w0, b0);
    bn_noise<<<BL / 2, 256>>>(Yp, nz0, 0);

    // layer 1: K=512
    gemm_mma<<<dim3(8, 2, 64), 256, GSMEM>>>(P1, Mh, Ml, Yp, HDIM, CDIM, 1, 1);
    bn_finalize<<<8, 128>>>(w1, b1);
    bn_noise<<<BL / 2, 256>>>(Yp, nz1, 1);

    // layer 2: K=512, M=144 (2 o-tiles, second partially valid)
    gemm_mma<<<dim3(2, 2, 64), 256, GSMEM>>>(P2, Mh, Ml, Y2p, HDIM, MOUT, 0, 0);

    // merged epilogue
    epilogue_kernel<<<BDIM, 128>>>(out);
}

// round 8
// speedup vs baseline: 1.3867x; 1.3867x over previous
#include <cuda_runtime.h>
#include <cuda_fp16.h>
#include <cstdint>

// Problem constants
#define BDIM  256          // B = BATCH*NBR
#define LDIM  64
#define DIN   64           // 2*K*U
#define HDIM  512
#define CDIM  1024         // 2*h
#define MOUT  144
#define BL    16384        // B*L
#define NS_STRIDE ((size_t)BL * HDIM)
#define OUT_FRE  0
#define OUT_FIM  524288
#define OUT_I    1048576

// ---------------- scratch ----------------
__device__ __align__(128) __half g_A0h[BDIM * LDIM * DIN];   // 2 MB
__device__ __align__(128) __half g_A0l[BDIM * LDIM * DIN];   // 2 MB
__device__ __align__(128) float g_Y [LDIM * BDIM * CDIM];    // 64 MB [n][b][o]
__device__ __align__(128) __half g_Mh[BL * HDIM];            // 16 MB [(b*64+n)][h]
__device__ __align__(128) __half g_Ml[BL * HDIM];            // 16 MB
__device__ __align__(128) float g_Y2[LDIM * BDIM * MOUT];    //  9 MB [n][b][c]
__device__ float g_pS [256 * CDIM];
__device__ float g_pS2[256 * CDIM];
__device__ float g_scale[CDIM];
__device__ float g_shift[CDIM];
__device__ float g_Ipart[BL];

// ================= helpers =================
__device__ __forceinline__ uint32_t smem_u32(const void* p) {
    uint32_t a;
    asm("{ .reg .u64 t; cvta.to.shared.u64 t, %1; cvt.u32.u64 %0, t; }" : "=r"(a) : "l"(p));
    return a;
}
__device__ __forceinline__ void ldmx4(uint32_t* r, uint32_t addr) {
    asm volatile("ldmatrix.sync.aligned.m8n8.x4.shared.b16 {%0,%1,%2,%3}, [%4];"
        : "=r"(r[0]), "=r"(r[1]), "=r"(r[2]), "=r"(r[3]) : "r"(addr));
}
__device__ __forceinline__ void mma_f16(float* c, const uint32_t* a,
                                        uint32_t b0, uint32_t b1) {
    asm volatile("mma.sync.aligned.m16n8k16.row.col.f32.f16.f16.f32 "
        "{%0,%1,%2,%3}, {%4,%5,%6,%7}, {%8,%9}, {%0,%1,%2,%3};"
        : "+f"(c[0]), "+f"(c[1]), "+f"(c[2]), "+f"(c[3])
        : "r"(a[0]), "r"(a[1]), "r"(a[2]), "r"(a[3]), "r"(b0), "r"(b1));
}
#define CP_ASYNC16(dst, src) \
    asm volatile("cp.async.ca.shared.global [%0], [%1], 16;" :: "r"(dst), "l"(src))
#define CP_COMMIT() asm volatile("cp.async.commit_group;")
#define CP_WAIT0()  asm volatile("cp.async.wait_group 0;")

__device__ __forceinline__ uint2 cvt4h(float4 v) {
    __half2 a = __floats2half2_rn(v.x, v.y);
    __half2 b = __floats2half2_rn(v.z, v.w);
    uint2 r;
    r.x = *reinterpret_cast<uint32_t*>(&a);
    r.y = *reinterpret_cast<uint32_t*>(&b);
    return r;
}

// ================= tensor-core batched GEMM (fp16 2-term: Ph*Ahi + Ph*Alo) ======
// Y[n][b][o] = sum_d P[n][o][d] * Act[(b*64+n)][d]
// CTA tile 128b x 128o x 64k; 8 warps (2b x 4o), warp tile 64x32.
// smem buffer: AH 16K | AL 16K | PH 16K ; double buffered (96 KB).
#define GBUF 49152
#define GSMEM (2 * GBUF)

__global__ __launch_bounds__(256) void gemm_mma(
    const float* __restrict__ Pw,
    const __half* __restrict__ Ah, const __half* __restrict__ Al,
    float* __restrict__ Y, int K, int M, int relu, int stats)
{
    extern __shared__ char sm[];
    const int tid = threadIdx.x, wid = tid >> 5, lid = tid & 31;
    const int m0 = blockIdx.x * 128, b0 = blockIdx.y * 128, n = blockIdx.z;
    const int nchunk = K >> 6;
    uint32_t sb = smem_u32(sm);

    // global-load indexing
    const int r0 = tid >> 4, c4 = tid & 15;
    const int cswP = (((c4 >> 1) ^ (r0 & 7)) << 4) + (c4 & 1) * 8;
    const int ac = c4 & 7;
    const int aregion = (c4 < 8) ? 0 : 16384;
    const int cswA = ((ac ^ (r0 & 7)) << 4);
    const __half* Asrc = (c4 < 8) ? Ah : Al;

    // ldmatrix lane geometry
    const int lr  = (lid & 7) + ((lid >> 3) & 1) * 8;
    const int kch = lid >> 4;
    const int warp_b = wid >> 2, warp_o = wid & 3;
    int rowA128[4], r7A[4], rowB128[2], r7B[2];
#pragma unroll
    for (int mm = 0; mm < 4; mm++) {
        int r = warp_b * 64 + mm * 16 + lr;
        rowA128[mm] = r * 128; r7A[mm] = r & 7;
    }
#pragma unroll
    for (int g = 0; g < 2; g++) {
        int r = warp_o * 32 + g * 16 + lr;
        rowB128[g] = r * 128; r7B[g] = r & 7;
    }

    float acc[4][4][4];
#pragma unroll
    for (int i = 0; i < 4; i++)
#pragma unroll
        for (int j = 0; j < 4; j++)
#pragma unroll
            for (int q = 0; q < 4; q++) acc[i][j][q] = 0.f;

    float4 stP[8];

    // ---- prologue: chunk 0 ----
#pragma unroll
    for (int j = 0; j < 8; j++) {
        int row = j * 16 + r0;
        const void* src = &Asrc[((size_t)(b0 + row) * 64 + n) * K + ac * 8];
        CP_ASYNC16(sb + aregion + row * 128 + cswA, src);
    }
    CP_COMMIT();
#pragma unroll
    for (int j = 0; j < 8; j++) {
        int row = j * 16 + r0;
        if (m0 + row < M)
            stP[j] = *(const float4*)&Pw[((size_t)n * M + m0 + row) * K + c4 * 4];
        else stP[j] = make_float4(0.f, 0.f, 0.f, 0.f);
    }
#pragma unroll
    for (int j = 0; j < 8; j++) {
        int row = j * 16 + r0;
        *(uint2*)(sm + 32768 + row * 128 + cswP) = cvt4h(stP[j]);
    }
    CP_WAIT0();
    __syncthreads();

    for (int c = 0; c < nchunk; c++) {
        if (c + 1 < nchunk) {
            int k0 = (c + 1) << 6;
            uint32_t bdst = sb + ((c + 1) & 1) * GBUF;
#pragma unroll
            for (int j = 0; j < 8; j++) {
                int row = j * 16 + r0;
                const void* src = &Asrc[((size_t)(b0 + row) * 64 + n) * K + k0 + ac * 8];
                CP_ASYNC16(bdst + aregion + row * 128 + cswA, src);
            }
            CP_COMMIT();
#pragma unroll
            for (int j = 0; j < 8; j++) {
                int row = j * 16 + r0;
                if (m0 + row < M)
                    stP[j] = *(const float4*)&Pw[((size_t)n * M + m0 + row) * K + k0 + c4 * 4];
                else stP[j] = make_float4(0.f, 0.f, 0.f, 0.f);
            }
        }

        // ---- compute on buffer c&1 ----
        uint32_t ub = sb + (c & 1) * GBUF;
#pragma unroll
        for (int kk = 0; kk < 4; kk++) {
            uint32_t ah[4][4], al[4][4], bh[2][4];
            int ksel = kk * 2 + kch;
#pragma unroll
            for (int mm = 0; mm < 4; mm++)
                ldmx4(ah[mm], ub + rowA128[mm] + ((ksel ^ r7A[mm]) << 4));
#pragma unroll
            for (int mm = 0; mm < 4; mm++)
                ldmx4(al[mm], ub + 16384 + rowA128[mm] + ((ksel ^ r7A[mm]) << 4));
#pragma unroll
            for (int g = 0; g < 2; g++)
                ldmx4(bh[g], ub + 32768 + rowB128[g] + ((ksel ^ r7B[g]) << 4));
#pragma unroll
            for (int mm = 0; mm < 4; mm++)
#pragma unroll
                for (int nn = 0; nn < 4; nn++) {
                    int g = nn >> 1, s = nn & 1;
                    mma_f16(acc[mm][nn], ah[mm], bh[g][s], bh[g][s + 2]);
                    mma_f16(acc[mm][nn], al[mm], bh[g][s], bh[g][s + 2]);
                }
        }

        if (c + 1 < nchunk) {
            char* buf = sm + ((c + 1) & 1) * GBUF;
#pragma unroll
            for (int j = 0; j < 8; j++) {
                int row = j * 16 + r0;
                *(uint2*)(buf + 32768 + row * 128 + cswP) = cvt4h(stP[j]);
            }
            CP_WAIT0();
        }
        __syncthreads();
    }

    // ---- epilogue ----
    if (relu) {
#pragma unroll
        for (int i = 0; i < 4; i++)
#pragma unroll
            for (int j = 0; j < 4; j++)
#pragma unroll
                for (int q = 0; q < 4; q++) acc[i][j][q] = fmaxf(acc[i][j][q], 0.f);
    }

#pragma unroll
    for (int mm = 0; mm < 4; mm++) {
        int bg = b0 + warp_b * 64 + mm * 16 + (lid >> 2);
#pragma unroll
        for (int nn = 0; nn < 4; nn++) {
            int og = m0 + warp_o * 32 + nn * 8 + (lid & 3) * 2;
            if (og < M) {
                float2 v01 = make_float2(acc[mm][nn][0], acc[mm][nn][1]);
                float2 v23 = make_float2(acc[mm][nn][2], acc[mm][nn][3]);
                *(float2*)&Y[((size_t)n * 256 + bg) * M + og] = v01;
                *(float2*)&Y[((size_t)n * 256 + bg + 8) * M + og] = v23;
            }
        }
    }

    // fused BN partial stats (deterministic per-slot, no atomics)
    if (stats) {
        float s1[8], s2v[8];
#pragma unroll
        for (int k = 0; k < 8; k++) { s1[k] = 0.f; s2v[k] = 0.f; }
#pragma unroll
        for (int nn = 0; nn < 4; nn++)
#pragma unroll
            for (int q = 0; q < 2; q++) {
                int k = nn * 2 + q;
#pragma unroll
                for (int mm = 0; mm < 4; mm++) {
                    float v0 = acc[mm][nn][q], v1 = acc[mm][nn][q + 2];
                    s1[k] += v0 + v1;
                    s2v[k] += v0 * v0 + v1 * v1;
                }
            }
#pragma unroll
        for (int k = 0; k < 8; k++)
#pragma unroll
            for (int msk = 4; msk <= 16; msk <<= 1) {
                s1[k]  += __shfl_xor_sync(0xFFFFFFFFu, s1[k],  msk);
                s2v[k] += __shfl_xor_sync(0xFFFFFFFFu, s2v[k], msk);
            }
        if ((lid >> 2) == 0) {
            int slot = (blockIdx.y * 64 + blockIdx.z) * 2 + warp_b;
#pragma unroll
            for (int nn = 0; nn < 4; nn++)
#pragma unroll
                for (int q = 0; q < 2; q++) {
                    int ch = m0 + warp_o * 32 + nn * 8 + (lid & 3) * 2 + q;
                    g_pS [slot * CDIM + ch] = s1[nn * 2 + q];
                    g_pS2[slot * CDIM + ch] = s2v[nn * 2 + q];
                }
        }
    }
}

// ================= pre/post kernels =================
__global__ void build_a0(const float* __restrict__ Hre, const float* __restrict__ Him) {
    int b = blockIdx.x, t = threadIdx.x;
    const float* hr = Hre + (size_t)b * 2048;
    const float* hi = Him + (size_t)b * 2048;
    size_t dbase = (size_t)b * 4096;
#pragma unroll
    for (int j = 0; j < 8; j++) {
        int idx = t + j * 256;
        int n = idx >> 5, d = idx & 31;
        float v0 = hr[idx], v1 = hi[idx];
        __half h0 = __float2half_rn(v0);
        __half h1 = __float2half_rn(v1);
        g_A0h[dbase + n * 64 + d]      = h0;
        g_A0h[dbase + n * 64 + 32 + d] = h1;
        g_A0l[dbase + n * 64 + d]      = __float2half_rn(v0 - __half2float(h0));
        g_A0l[dbase + n * 64 + 32 + d] = __float2half_rn(v1 - __half2float(h1));
    }
}

// spacer: shifts launch indices so ncu (-s 5 -c 1) captures the layer-1 GEMM
__global__ void spacer_kernel() {}

// slot-parallel BN finalize: 32 blocks x 256 thr; block covers 32 channels,
// 8 slot-groups of 32 slots each, tree-reduced in smem. Deterministic order.
__global__ void bn_finalize(const float* __restrict__ w, const float* __restrict__ bb) {
    int c = blockIdx.x * 32 + (threadIdx.x & 31);
    int g = threadIdx.x >> 5;   // 0..7
    float s = 0.f, s2 = 0.f;
#pragma unroll
    for (int i = 0; i < 32; i++) {
        int sl = g * 32 + i;
        s  += g_pS [sl * CDIM + c];
        s2 += g_pS2[sl * CDIM + c];
    }
    __shared__ float a1[8][32], a2[8][32];
    a1[g][threadIdx.x & 31] = s;
    a2[g][threadIdx.x & 31] = s2;
    __syncthreads();
    if (g == 0) {
        float ts = 0.f, ts2 = 0.f;
#pragma unroll
        for (int j = 0; j < 8; j++) { ts += a1[j][threadIdx.x & 31]; ts2 += a2[j][threadIdx.x & 31]; }
        float mean = ts / (float)BL;
        float var  = ts2 / (float)BL - mean * mean;
        float sc = w[c] * rsqrtf(var + 1e-5f);
        g_scale[c] = sc;
        g_shift[c] = bb[c] - mean * sc;
    }
}

// fused BN-apply + softplus + closed-form noise MI; vectorized float4, 128 thr/blk
__global__ void bn_noise(const float* __restrict__ Y, const float* __restrict__ Nz, int add) {
    int nb = blockIdx.x, t = threadIdx.x;
    int n = nb >> 8, b = nb & 255;
    size_t ybase = (size_t)nb * CDIM;
    size_t bl = (size_t)b * 64 + n;
    size_t mbase = bl * HDIM;
    int d = t * 4;

    float4 ym = *(const float4*)&Y[ybase + d];
    float4 ys = *(const float4*)&Y[ybase + HDIM + d];
    float4 scm = *(const float4*)&g_scale[d];
    float4 shm = *(const float4*)&g_shift[d];
    float4 scs = *(const float4*)&g_scale[HDIM + d];
    float4 shs = *(const float4*)&g_shift[HDIM + d];
    float4 n0 = *(const float4*)&Nz[mbase + d];
    float4 n1 = *(const float4*)&Nz[mbase + d + NS_STRIDE];
    float4 n2 = *(const float4*)&Nz[mbase + d + 2 * NS_STRIDE];
    float4 n3 = *(const float4*)&Nz[mbase + d + 3 * NS_STRIDE];

    float m[4] = { scm.x * ym.x + shm.x, scm.y * ym.y + shm.y,
                   scm.z * ym.z + shm.z, scm.w * ym.w + shm.w };
    float x[4] = { scs.x * ys.x + shs.x, scs.y * ys.y + shs.y,
                   scs.z * ys.z + shs.z, scs.w * ys.w + shs.w };
    float nn0[4] = { n0.x, n0.y, n0.z, n0.w };
    float nn1[4] = { n1.x, n1.y, n1.z, n1.w };
    float nn2[4] = { n2.x, n2.y, n2.z, n2.w };
    float nn3[4] = { n3.x, n3.y, n3.z, n3.w };

    float local = 0.f;
    float lo[4];
#pragma unroll
    for (int i = 0; i < 4; i++) {
        float s = fmaxf(x[i], 0.f) + log1pf(__expf(-fabsf(x[i]))) + 1e-10f;
        float S1 = (nn0[i] + nn1[i] + nn2[i] + nn3[i]) * 0.25f;
        float S2 = (nn0[i] * nn0[i] + nn1[i] * nn1[i] +
                    nn2[i] * nn2[i] + nn3[i] * nn3[i]) * 0.25f;
        local += 0.5f * m[i] * m[i] - __logf(s) + m[i] * s * S1
               + 0.5f * (s * s - 1.0f) * S2;
        __half mh = __float2half_rn(m[i]);
        lo[i] = m[i] - __half2float(mh);
        m[i] = __half2float(mh);
    }
    __half2 mh01 = __floats2half2_rn(m[0], m[1]);
    __half2 mh23 = __floats2half2_rn(m[2], m[3]);
    __half2 ml01 = __floats2half2_rn(lo[0], lo[1]);
    __half2 ml23 = __floats2half2_rn(lo[2], lo[3]);
    uint2 hv, lv;
    hv.x = *reinterpret_cast<uint32_t*>(&mh01);
    hv.y = *reinterpret_cast<uint32_t*>(&mh23);
    lv.x = *reinterpret_cast<uint32_t*>(&ml01);
    lv.y = *reinterpret_cast<uint32_t*>(&ml23);
    *(uint2*)&g_Mh[mbase + d] = hv;
    *(uint2*)&g_Ml[mbase + d] = lv;

    __shared__ float sh[128];
    sh[t] = local;
    __syncthreads();
    for (int off = 64; off; off >>= 1) {
        if (t < off) sh[t] += sh[t + off];
        __syncthreads();
    }
    if (t == 0) {
        if (add) g_Ipart[bl] += sh[0];
        else     g_Ipart[bl]  = sh[0];
    }
}

// merged pn + final + I-sum: one block per b (256 blocks, 128 threads)
__global__ void epilogue_kernel(float* __restrict__ out) {
    int b = blockIdx.x, t = threadIdx.x;
    __shared__ float v[64][72];
    __shared__ float pk[64];
    __shared__ float Pn[8];
    __shared__ float mult[64][8];

    for (int idx = t; idx < 64 * 72; idx += 128) {
        int n = idx / 72, c = idx % 72;
        v[n][c] = g_Y2[((size_t)(n * 256 + b)) * MOUT + c];
    }
    __syncthreads();
    if (t < 64) {
        int k = t & 7, j = t >> 3;
        float s = 0.f;
#pragma unroll
        for (int n = j; n < 64; n += 8) { float x = v[n][64 + k]; s += x * x; }
        pk[t] = s;
    }
    __syncthreads();
    if (t < 8) {
        float tot = 0.f;
#pragma unroll
        for (int j = 0; j < 8; j++) tot += pk[j * 8 + t];
        Pn[t] = sqrtf(tot);
    }
    __syncthreads();
    for (int idx = t; idx < 512; idx += 128) {
        int n = idx >> 3, k = idx & 7;
        float ss = 0.f;
#pragma unroll
        for (int u = 0; u < 4; u++) {
            float a = v[n][k * 4 + u], c2 = v[n][32 + k * 4 + u];
            ss += a * a + c2 * c2;
        }
        mult[n][k] = v[n][64 + k] / Pn[k] * 8.0f / sqrtf(ss);  // sqrt(L)=8
    }
    __syncthreads();
    for (int idx = t; idx < 64 * 32; idx += 128) {
        int n = idx >> 5, c = idx & 31;
        size_t obase = ((size_t)b * 64 + n) * 32;
        float mlt = mult[n][c >> 2];
        out[OUT_FRE + obase + c] = v[n][c] * mlt;
        out[OUT_FIM + obase + c] = v[n][32 + c] * mlt;
    }
    if (t < 64) pk[t] = g_Ipart[(size_t)b * 64 + t];
    __syncthreads();
    if (t == 0) {
        float s = 0.f;
#pragma unroll
        for (int n = 0; n < 64; n++) s += pk[n];
        out[OUT_I + b] = s;
    }
}

// ================= launch =================
extern "C" void kernel_launch(void* const* d_in, const int* in_sizes, int n_in,
                              void* d_out, int out_size) {
    const float* Hre = (const float*)d_in[0];
    const float* Him = (const float*)d_in[1];
    const float* P0  = (const float*)d_in[2];
    const float* P1  = (const float*)d_in[3];
    const float* P2  = (const float*)d_in[4];
    const float* w0  = (const float*)d_in[5];
    const float* b0  = (const float*)d_in[6];
    const float* w1  = (const float*)d_in[7];
    const float* b1  = (const float*)d_in[8];
    const float* nz0 = (const float*)d_in[9];
    const float* nz1 = (const float*)d_in[10];
    float* out = (float*)d_out;

    float *Yp, *Y2p;
    __half *A0h, *A0l, *Mh, *Ml;
    cudaGetSymbolAddress((void**)&A0h, g_A0h);
    cudaGetSymbolAddress((void**)&A0l, g_A0l);
    cudaGetSymbolAddress((void**)&Yp,  g_Y);
    cudaGetSymbolAddress((void**)&Mh,  g_Mh);
    cudaGetSymbolAddress((void**)&Ml,  g_Ml);
    cudaGetSymbolAddress((void**)&Y2p, g_Y2);

    cudaFuncSetAttribute(gemm_mma, cudaFuncAttributeMaxDynamicSharedMemorySize, GSMEM);

    // layer 0: K=64                                   launch idx
    build_a0<<<BDIM, 256>>>(Hre, Him);                       // 0
    gemm_mma<<<dim3(8, 2, 64), 256, GSMEM>>>(P0, A0h, A0l, Yp, DIN, CDIM, 1, 1);  // 1
    bn_finalize<<<32, 256>>>(w0, b0);                        // 2
    bn_noise<<<BL, 128>>>(Yp, nz0, 0);                       // 3
    spacer_kernel<<<1, 32>>>();                              // 4

    // layer 1: K=512 — lands at index 5 for ncu -s 5 -c 1
    gemm_mma<<<dim3(8, 2, 64), 256, GSMEM>>>(P1, Mh, Ml, Yp, HDIM, CDIM, 1, 1);   // 5
    bn_finalize<<<32, 256>>>(w1, b1);                        // 6
    bn_noise<<<BL, 128>>>(Yp, nz1, 1);                       // 7

    // layer 2: K=512, M=144
    gemm_mma<<<dim3(2, 2, 64), 256, GSMEM>>>(P2, Mh, Ml, Y2p, HDIM, MOUT, 0, 0);  // 8

    // merged epilogue
    epilogue_kernel<<<BDIM, 128>>>(out);                     // 9
}

// round 9
// speedup vs baseline: 1.4121x; 1.0184x over previous
#include <cuda_runtime.h>
#include <cuda_fp16.h>
#include <cstdint>

// Problem constants
#define BDIM  256          // B = BATCH*NBR
#define LDIM  64
#define DIN   64           // 2*K*U
#define HDIM  512
#define CDIM  1024         // 2*h
#define MOUT  144
#define BL    16384        // B*L
#define NS_STRIDE ((size_t)BL * HDIM)
#define OUT_FRE  0
#define OUT_FIM  524288
#define OUT_I    1048576

// ---------------- scratch ----------------
__device__ __align__(128) __half g_A0h[BDIM * LDIM * DIN];   // 2 MB
__device__ __align__(128) __half g_A0l[BDIM * LDIM * DIN];   // 2 MB
__device__ __align__(128) float g_Y [LDIM * BDIM * CDIM];    // 64 MB [n][b][o]
__device__ __align__(128) __half g_Mh[BL * HDIM];            // 16 MB [(b*64+n)][h]
__device__ __align__(128) __half g_Ml[BL * HDIM];            // 16 MB
__device__ __align__(128) float g_Y2[LDIM * BDIM * MOUT];    //  9 MB [n][b][c]
__device__ float g_pS [256 * CDIM];
__device__ float g_pS2[256 * CDIM];
__device__ float g_scale[CDIM];
__device__ float g_shift[CDIM];
__device__ float g_Ipart[BL];

// ================= helpers =================
__device__ __forceinline__ uint32_t smem_u32(const void* p) {
    uint32_t a;
    asm("{ .reg .u64 t; cvta.to.shared.u64 t, %1; cvt.u32.u64 %0, t; }" : "=r"(a) : "l"(p));
    return a;
}
__device__ __forceinline__ void ldmx4(uint32_t* r, uint32_t addr) {
    asm volatile("ldmatrix.sync.aligned.m8n8.x4.shared.b16 {%0,%1,%2,%3}, [%4];"
        : "=r"(r[0]), "=r"(r[1]), "=r"(r[2]), "=r"(r[3]) : "r"(addr));
}
__device__ __forceinline__ void mma_f16(float* c, const uint32_t* a,
                                        uint32_t b0, uint32_t b1) {
    asm volatile("mma.sync.aligned.m16n8k16.row.col.f32.f16.f16.f32 "
        "{%0,%1,%2,%3}, {%4,%5,%6,%7}, {%8,%9}, {%0,%1,%2,%3};"
        : "+f"(c[0]), "+f"(c[1]), "+f"(c[2]), "+f"(c[3])
        : "r"(a[0]), "r"(a[1]), "r"(a[2]), "r"(a[3]), "r"(b0), "r"(b1));
}
// f16-accumulate variant for the small correction term (Ph*Al)
__device__ __forceinline__ void mma_f16acc(uint32_t* c, const uint32_t* a,
                                           uint32_t b0, uint32_t b1) {
    asm volatile("mma.sync.aligned.m16n8k16.row.col.f16.f16.f16.f16 "
        "{%0,%1}, {%2,%3,%4,%5}, {%6,%7}, {%0,%1};"
        : "+r"(c[0]), "+r"(c[1])
        : "r"(a[0]), "r"(a[1]), "r"(a[2]), "r"(a[3]), "r"(b0), "r"(b1));
}
#define CP_ASYNC16(dst, src) \
    asm volatile("cp.async.ca.shared.global [%0], [%1], 16;" :: "r"(dst), "l"(src))
#define CP_COMMIT() asm volatile("cp.async.commit_group;")
#define CP_WAIT0()  asm volatile("cp.async.wait_group 0;")

__device__ __forceinline__ uint2 cvt4h(float4 v) {
    __half2 a = __floats2half2_rn(v.x, v.y);
    __half2 b = __floats2half2_rn(v.z, v.w);
    uint2 r;
    r.x = *reinterpret_cast<uint32_t*>(&a);
    r.y = *reinterpret_cast<uint32_t*>(&b);
    return r;
}

// ================= tensor-core batched GEMM =================
// 2-term fp16: Ph*Ahi (f32 acc) + Ph*Alo (f16 acc — small correction)
// Y[n][b][o] = sum_d P[n][o][d] * Act[(b*64+n)][d]
// CTA tile 128b x 128o x 64k; 8 warps (2b x 4o), warp tile 64x32.
// All launches use full tiles (no M predicates).
// smem buffer: AH 16K | AL 16K | PH 16K ; double buffered (96 KB).
#define GBUF 49152
#define GSMEM (2 * GBUF)

__global__ __launch_bounds__(256) void gemm_mma(
    const float* __restrict__ Pw,
    const __half* __restrict__ Ah, const __half* __restrict__ Al,
    float* __restrict__ Y, int K, int M, int relu, int stats)
{
    extern __shared__ char sm[];
    const int tid = threadIdx.x, wid = tid >> 5, lid = tid & 31;
    const int m0 = blockIdx.x * 128, b0 = blockIdx.y * 128, n = blockIdx.z;
    const int nchunk = K >> 6;
    uint32_t sb = smem_u32(sm);

    // global-load indexing
    const int r0 = tid >> 4, c4 = tid & 15;
    const int cswP = (((c4 >> 1) ^ (r0 & 7)) << 4) + (c4 & 1) * 8;
    const int ac = c4 & 7;
    const int aregion = (c4 < 8) ? 0 : 16384;
    const int cswA = ((ac ^ (r0 & 7)) << 4);
    const __half* Asrc = (c4 < 8) ? Ah : Al;

    // ldmatrix lane geometry
    const int lr  = (lid & 7) + ((lid >> 3) & 1) * 8;
    const int kch = lid >> 4;
    const int warp_b = wid >> 2, warp_o = wid & 3;
    int rowA128[4], r7A[4], rowB128[2], r7B[2];
#pragma unroll
    for (int mm = 0; mm < 4; mm++) {
        int r = warp_b * 64 + mm * 16 + lr;
        rowA128[mm] = r * 128; r7A[mm] = r & 7;
    }
#pragma unroll
    for (int g = 0; g < 2; g++) {
        int r = warp_o * 32 + g * 16 + lr;
        rowB128[g] = r * 128; r7B[g] = r & 7;
    }

    float acc[4][4][4];
    uint32_t acc16[4][4][2];
#pragma unroll
    for (int i = 0; i < 4; i++)
#pragma unroll
        for (int j = 0; j < 4; j++) {
#pragma unroll
            for (int q = 0; q < 4; q++) acc[i][j][q] = 0.f;
            acc16[i][j][0] = 0u; acc16[i][j][1] = 0u;
        }

    float4 stP[8];

    // ---- prologue: chunk 0 ----
#pragma unroll
    for (int j = 0; j < 8; j++) {
        int row = j * 16 + r0;
        const void* src = &Asrc[((size_t)(b0 + row) * 64 + n) * K + ac * 8];
        CP_ASYNC16(sb + aregion + row * 128 + cswA, src);
    }
    CP_COMMIT();
#pragma unroll
    for (int j = 0; j < 8; j++) {
        int row = j * 16 + r0;
        stP[j] = *(const float4*)&Pw[((size_t)n * M + m0 + row) * K + c4 * 4];
    }
#pragma unroll
    for (int j = 0; j < 8; j++) {
        int row = j * 16 + r0;
        *(uint2*)(sm + 32768 + row * 128 + cswP) = cvt4h(stP[j]);
    }
    CP_WAIT0();
    __syncthreads();

    for (int c = 0; c < nchunk; c++) {
        if (c + 1 < nchunk) {
            int k0 = (c + 1) << 6;
            uint32_t bdst = sb + ((c + 1) & 1) * GBUF;
#pragma unroll
            for (int j = 0; j < 8; j++) {
                int row = j * 16 + r0;
                const void* src = &Asrc[((size_t)(b0 + row) * 64 + n) * K + k0 + ac * 8];
                CP_ASYNC16(bdst + aregion + row * 128 + cswA, src);
            }
            CP_COMMIT();
#pragma unroll
            for (int j = 0; j < 8; j++) {
                int row = j * 16 + r0;
                stP[j] = *(const float4*)&Pw[((size_t)n * M + m0 + row) * K + k0 + c4 * 4];
            }
        }

        // ---- compute on buffer c&1 ----
        uint32_t ub = sb + (c & 1) * GBUF;
#pragma unroll
        for (int kk = 0; kk < 4; kk++) {
            uint32_t ah[4][4], al[4][4], bh[2][4];
            int ksel = kk * 2 + kch;
#pragma unroll
            for (int mm = 0; mm < 4; mm++)
                ldmx4(ah[mm], ub + rowA128[mm] + ((ksel ^ r7A[mm]) << 4));
#pragma unroll
            for (int mm = 0; mm < 4; mm++)
                ldmx4(al[mm], ub + 16384 + rowA128[mm] + ((ksel ^ r7A[mm]) << 4));
#pragma unroll
            for (int g = 0; g < 2; g++)
                ldmx4(bh[g], ub + 32768 + rowB128[g] + ((ksel ^ r7B[g]) << 4));
#pragma unroll
            for (int mm = 0; mm < 4; mm++)
#pragma unroll
                for (int nn = 0; nn < 4; nn++) {
                    int g = nn >> 1, s = nn & 1;
                    mma_f16(acc[mm][nn], ah[mm], bh[g][s], bh[g][s + 2]);
                    mma_f16acc(acc16[mm][nn], al[mm], bh[g][s], bh[g][s + 2]);
                }
        }

        if (c + 1 < nchunk) {
            char* buf = sm + ((c + 1) & 1) * GBUF;
#pragma unroll
            for (int j = 0; j < 8; j++) {
                int row = j * 16 + r0;
                *(uint2*)(buf + 32768 + row * 128 + cswP) = cvt4h(stP[j]);
            }
            CP_WAIT0();
        }
        __syncthreads();
    }

    // ---- merge f16 correction + relu ----
#pragma unroll
    for (int i = 0; i < 4; i++)
#pragma unroll
        for (int j = 0; j < 4; j++) {
            __half2 p0 = *reinterpret_cast<__half2*>(&acc16[i][j][0]);
            __half2 p1 = *reinterpret_cast<__half2*>(&acc16[i][j][1]);
            acc[i][j][0] += __low2float(p0);
            acc[i][j][1] += __high2float(p0);
            acc[i][j][2] += __low2float(p1);
            acc[i][j][3] += __high2float(p1);
        }
    if (relu) {
#pragma unroll
        for (int i = 0; i < 4; i++)
#pragma unroll
            for (int j = 0; j < 4; j++)
#pragma unroll
                for (int q = 0; q < 4; q++) acc[i][j][q] = fmaxf(acc[i][j][q], 0.f);
    }

#pragma unroll
    for (int mm = 0; mm < 4; mm++) {
        int bg = b0 + warp_b * 64 + mm * 16 + (lid >> 2);
#pragma unroll
        for (int nn = 0; nn < 4; nn++) {
            int og = m0 + warp_o * 32 + nn * 8 + (lid & 3) * 2;
            float2 v01 = make_float2(acc[mm][nn][0], acc[mm][nn][1]);
            float2 v23 = make_float2(acc[mm][nn][2], acc[mm][nn][3]);
            *(float2*)&Y[((size_t)n * 256 + bg) * M + og] = v01;
            *(float2*)&Y[((size_t)n * 256 + bg + 8) * M + og] = v23;
        }
    }

    // fused BN partial stats (deterministic per-slot, no atomics)
    if (stats) {
        float s1[8], s2v[8];
#pragma unroll
        for (int k = 0; k < 8; k++) { s1[k] = 0.f; s2v[k] = 0.f; }
#pragma unroll
        for (int nn = 0; nn < 4; nn++)
#pragma unroll
            for (int q = 0; q < 2; q++) {
                int k = nn * 2 + q;
#pragma unroll
                for (int mm = 0; mm < 4; mm++) {
                    float v0 = acc[mm][nn][q], v1 = acc[mm][nn][q + 2];
                    s1[k] += v0 + v1;
                    s2v[k] += v0 * v0 + v1 * v1;
                }
            }
#pragma unroll
        for (int k = 0; k < 8; k++)
#pragma unroll
            for (int msk = 4; msk <= 16; msk <<= 1) {
                s1[k]  += __shfl_xor_sync(0xFFFFFFFFu, s1[k],  msk);
                s2v[k] += __shfl_xor_sync(0xFFFFFFFFu, s2v[k], msk);
            }
        if ((lid >> 2) == 0) {
            int slot = (blockIdx.y * 64 + blockIdx.z) * 2 + warp_b;
#pragma unroll
            for (int nn = 0; nn < 4; nn++)
#pragma unroll
                for (int q = 0; q < 2; q++) {
                    int ch = m0 + warp_o * 32 + nn * 8 + (lid & 3) * 2 + q;
                    g_pS [slot * CDIM + ch] = s1[nn * 2 + q];
                    g_pS2[slot * CDIM + ch] = s2v[nn * 2 + q];
                }
        }
    }
}

// ================= pre/post kernels =================
__global__ void build_a0(const float* __restrict__ Hre, const float* __restrict__ Him) {
    int b = blockIdx.x, t = threadIdx.x;
    const float* hr = Hre + (size_t)b * 2048;
    const float* hi = Him + (size_t)b * 2048;
    size_t dbase = (size_t)b * 4096;
#pragma unroll
    for (int j = 0; j < 8; j++) {
        int idx = t + j * 256;
        int n = idx >> 5, d = idx & 31;
        float v0 = hr[idx], v1 = hi[idx];
        __half h0 = __float2half_rn(v0);
        __half h1 = __float2half_rn(v1);
        g_A0h[dbase + n * 64 + d]      = h0;
        g_A0h[dbase + n * 64 + 32 + d] = h1;
        g_A0l[dbase + n * 64 + d]      = __float2half_rn(v0 - __half2float(h0));
        g_A0l[dbase + n * 64 + 32 + d] = __float2half_rn(v1 - __half2float(h1));
    }
}

// slot-parallel BN finalize: 32 blocks x 256 thr
__global__ void bn_finalize(const float* __restrict__ w, const float* __restrict__ bb) {
    int c = blockIdx.x * 32 + (threadIdx.x & 31);
    int g = threadIdx.x >> 5;   // 0..7
    float s = 0.f, s2 = 0.f;
#pragma unroll
    for (int i = 0; i < 32; i++) {
        int sl = g * 32 + i;
        s  += g_pS [sl * CDIM + c];
        s2 += g_pS2[sl * CDIM + c];
    }
    __shared__ float a1[8][32], a2[8][32];
    a1[g][threadIdx.x & 31] = s;
    a2[g][threadIdx.x & 31] = s2;
    __syncthreads();
    if (g == 0) {
        float ts = 0.f, ts2 = 0.f;
#pragma unroll
        for (int j = 0; j < 8; j++) { ts += a1[j][threadIdx.x & 31]; ts2 += a2[j][threadIdx.x & 31]; }
        float mean = ts / (float)BL;
        float var  = ts2 / (float)BL - mean * mean;
        float sc = w[c] * rsqrtf(var + 1e-5f);
        g_scale[c] = sc;
        g_shift[c] = bb[c] - mean * sc;
    }
}

// fused BN-apply + softplus + closed-form noise MI; vectorized float4, 128 thr/blk
__global__ void bn_noise(const float* __restrict__ Y, const float* __restrict__ Nz, int add) {
    int nb = blockIdx.x, t = threadIdx.x;
    int n = nb >> 8, b = nb & 255;
    size_t ybase = (size_t)nb * CDIM;
    size_t bl = (size_t)b * 64 + n;
    size_t mbase = bl * HDIM;
    int d = t * 4;

    float4 ym = *(const float4*)&Y[ybase + d];
    float4 ys = *(const float4*)&Y[ybase + HDIM + d];
    float4 scm = *(const float4*)&g_scale[d];
    float4 shm = *(const float4*)&g_shift[d];
    float4 scs = *(const float4*)&g_scale[HDIM + d];
    float4 shs = *(const float4*)&g_shift[HDIM + d];
    float4 n0 = *(const float4*)&Nz[mbase + d];
    float4 n1 = *(const float4*)&Nz[mbase + d + NS_STRIDE];
    float4 n2 = *(const float4*)&Nz[mbase + d + 2 * NS_STRIDE];
    float4 n3 = *(const float4*)&Nz[mbase + d + 3 * NS_STRIDE];

    float m[4] = { scm.x * ym.x + shm.x, scm.y * ym.y + shm.y,
                   scm.z * ym.z + shm.z, scm.w * ym.w + shm.w };
    float x[4] = { scs.x * ys.x + shs.x, scs.y * ys.y + shs.y,
                   scs.z * ys.z + shs.z, scs.w * ys.w + shs.w };
    float nn0[4] = { n0.x, n0.y, n0.z, n0.w };
    float nn1[4] = { n1.x, n1.y, n1.z, n1.w };
    float nn2[4] = { n2.x, n2.y, n2.z, n2.w };
    float nn3[4] = { n3.x, n3.y, n3.z, n3.w };

    float local = 0.f;
    float lo[4];
#pragma unroll
    for (int i = 0; i < 4; i++) {
        float s = fmaxf(x[i], 0.f) + log1pf(__expf(-fabsf(x[i]))) + 1e-10f;
        float S1 = (nn0[i] + nn1[i] + nn2[i] + nn3[i]) * 0.25f;
        float S2 = (nn0[i] * nn0[i] + nn1[i] * nn1[i] +
                    nn2[i] * nn2[i] + nn3[i] * nn3[i]) * 0.25f;
        local += 0.5f * m[i] * m[i] - __logf(s) + m[i] * s * S1
               + 0.5f * (s * s - 1.0f) * S2;
        __half mh = __float2half_rn(m[i]);
        lo[i] = m[i] - __half2float(mh);
        m[i] = __half2float(mh);
    }
    __half2 mh01 = __floats2half2_rn(m[0], m[1]);
    __half2 mh23 = __floats2half2_rn(m[2], m[3]);
    __half2 ml01 = __floats2half2_rn(lo[0], lo[1]);
    __half2 ml23 = __floats2half2_rn(lo[2], lo[3]);
    uint2 hv, lv;
    hv.x = *reinterpret_cast<uint32_t*>(&mh01);
    hv.y = *reinterpret_cast<uint32_t*>(&mh23);
    lv.x = *reinterpret_cast<uint32_t*>(&ml01);
    lv.y = *reinterpret_cast<uint32_t*>(&ml23);
    *(uint2*)&g_Mh[mbase + d] = hv;
    *(uint2*)&g_Ml[mbase + d] = lv;

    __shared__ float sh[128];
    sh[t] = local;
    __syncthreads();
    for (int off = 64; off; off >>= 1) {
        if (t < off) sh[t] += sh[t + off];
        __syncthreads();
    }
    if (t == 0) {
        if (add) g_Ipart[bl] += sh[0];
        else     g_Ipart[bl]  = sh[0];
    }
}

// merged pn + final + I-sum: one block per b (256 blocks, 128 threads)
__global__ void epilogue_kernel(float* __restrict__ out) {
    int b = blockIdx.x, t = threadIdx.x;
    __shared__ float v[64][72];
    __shared__ float pk[64];
    __shared__ float Pn[8];
    __shared__ float mult[64][8];

    for (int idx = t; idx < 64 * 72; idx += 128) {
        int n = idx / 72, c = idx % 72;
        v[n][c] = g_Y2[((size_t)(n * 256 + b)) * MOUT + c];
    }
    __syncthreads();
    if (t < 64) {
        int k = t & 7, j = t >> 3;
        float s = 0.f;
#pragma unroll
        for (int n = j; n < 64; n += 8) { float x = v[n][64 + k]; s += x * x; }
        pk[t] = s;
    }
    __syncthreads();
    if (t < 8) {
        float tot = 0.f;
#pragma unroll
        for (int j = 0; j < 8; j++) tot += pk[j * 8 + t];
        Pn[t] = sqrtf(tot);
    }
    __syncthreads();
    for (int idx = t; idx < 512; idx += 128) {
        int n = idx >> 3, k = idx & 7;
        float ss = 0.f;
#pragma unroll
        for (int u = 0; u < 4; u++) {
            float a = v[n][k * 4 + u], c2 = v[n][32 + k * 4 + u];
            ss += a * a + c2 * c2;
        }
        mult[n][k] = v[n][64 + k] / Pn[k] * 8.0f / sqrtf(ss);  // sqrt(L)=8
    }
    __syncthreads();
    for (int idx = t; idx < 64 * 32; idx += 128) {
        int n = idx >> 5, c = idx & 31;
        size_t obase = ((size_t)b * 64 + n) * 32;
        float mlt = mult[n][c >> 2];
        out[OUT_FRE + obase + c] = v[n][c] * mlt;
        out[OUT_FIM + obase + c] = v[n][32 + c] * mlt;
    }
    if (t < 64) pk[t] = g_Ipart[(size_t)b * 64 + t];
    __syncthreads();
    if (t == 0) {
        float s = 0.f;
#pragma unroll
        for (int n = 0; n < 64; n++) s += pk[n];
        out[OUT_I + b] = s;
    }
}

// ================= launch =================
extern "C" void kernel_launch(void* const* d_in, const int* in_sizes, int n_in,
                              void* d_out, int out_size) {
    const float* Hre = (const float*)d_in[0];
    const float* Him = (const float*)d_in[1];
    const float* P0  = (const float*)d_in[2];
    const float* P1  = (const float*)d_in[3];
    const float* P2  = (const float*)d_in[4];
    const float* w0  = (const float*)d_in[5];
    const float* b0  = (const float*)d_in[6];
    const float* w1  = (const float*)d_in[7];
    const float* b1  = (const float*)d_in[8];
    const float* nz0 = (const float*)d_in[9];
    const float* nz1 = (const float*)d_in[10];
    float* out = (float*)d_out;

    float *Yp, *Y2p;
    __half *A0h, *A0l, *Mh, *Ml;
    cudaGetSymbolAddress((void**)&A0h, g_A0h);
    cudaGetSymbolAddress((void**)&A0l, g_A0l);
    cudaGetSymbolAddress((void**)&Yp,  g_Y);
    cudaGetSymbolAddress((void**)&Mh,  g_Mh);
    cudaGetSymbolAddress((void**)&Ml,  g_Ml);
    cudaGetSymbolAddress((void**)&Y2p, g_Y2);

    cudaFuncSetAttribute(gemm_mma, cudaFuncAttributeMaxDynamicSharedMemorySize, GSMEM);

    // layer 0: K=64
    build_a0<<<BDIM, 256>>>(Hre, Him);
    gemm_mma<<<dim3(8, 2, 64), 256, GSMEM>>>(P0, A0h, A0l, Yp, DIN, CDIM, 1, 1);
    bn_finalize<<<32, 256>>>(w0, b0);
    bn_noise<<<BL, 128>>>(Yp, nz0, 0);

    // layer 1: K=512
    gemm_mma<<<dim3(8, 2, 64), 256, GSMEM>>>(P1, Mh, Ml, Yp, HDIM, CDIM, 1, 1);
    bn_finalize<<<32, 256>>>(w1, b1);
    bn_noise<<<BL, 128>>>(Yp, nz1, 1);

    // layer 2: K=512 — only channels 0..127 are ever read (epilogue uses c<72)
    gemm_mma<<<dim3(1, 2, 64), 256, GSMEM>>>(P2, Mh, Ml, Y2p, HDIM, MOUT, 0, 0);

    // merged epilogue
    epilogue_kernel<<<BDIM, 128>>>(out);
}

// round 10
// speedup vs baseline: 1.4191x; 1.0049x over previous
#include <cuda_runtime.h>
#include <cuda_fp16.h>
#include <cstdint>

// Problem constants
#define BDIM  256          // B = BATCH*NBR
#define LDIM  64
#define DIN   64           // 2*K*U
#define HDIM  512
#define CDIM  1024         // 2*h
#define MOUT  144
#define BL    16384        // B*L
#define NS_STRIDE ((size_t)BL * HDIM)
#define OUT_FRE  0
#define OUT_FIM  524288
#define OUT_I    1048576

// ---------------- scratch ----------------
__device__ __align__(128) __half g_A0h[BDIM * LDIM * DIN];   // 2 MB
__device__ __align__(128) __half g_A0l[BDIM * LDIM * DIN];   // 2 MB
__device__ __align__(128) float g_Y [LDIM * BDIM * CDIM];    // 64 MB [n][b][o]
__device__ __align__(128) __half g_Mh[BL * HDIM];            // 16 MB [(b*64+n)][h]
__device__ __align__(128) __half g_Ml[BL * HDIM];            // 16 MB
__device__ __align__(128) float g_Y2[LDIM * BDIM * MOUT];    //  9 MB [n][b][c]
__device__ float g_pS [256 * CDIM];
__device__ float g_pS2[256 * CDIM];
__device__ float g_scale[CDIM];
__device__ float g_shift[CDIM];
__device__ float g_Ipart[BL];

// ================= helpers =================
__device__ __forceinline__ uint32_t smem_u32(const void* p) {
    uint32_t a;
    asm("{ .reg .u64 t; cvta.to.shared.u64 t, %1; cvt.u32.u64 %0, t; }" : "=r"(a) : "l"(p));
    return a;
}
__device__ __forceinline__ void ldmx4(uint32_t* r, uint32_t addr) {
    asm volatile("ldmatrix.sync.aligned.m8n8.x4.shared.b16 {%0,%1,%2,%3}, [%4];"
        : "=r"(r[0]), "=r"(r[1]), "=r"(r[2]), "=r"(r[3]) : "r"(addr));
}
__device__ __forceinline__ void mma_f16(float* c, const uint32_t* a,
                                        uint32_t b0, uint32_t b1) {
    asm volatile("mma.sync.aligned.m16n8k16.row.col.f32.f16.f16.f32 "
        "{%0,%1,%2,%3}, {%4,%5,%6,%7}, {%8,%9}, {%0,%1,%2,%3};"
        : "+f"(c[0]), "+f"(c[1]), "+f"(c[2]), "+f"(c[3])
        : "r"(a[0]), "r"(a[1]), "r"(a[2]), "r"(a[3]), "r"(b0), "r"(b1));
}
// f16-accumulate variant for the small correction term (Ph*Al)
__device__ __forceinline__ void mma_f16acc(uint32_t* c, const uint32_t* a,
                                           uint32_t b0, uint32_t b1) {
    asm volatile("mma.sync.aligned.m16n8k16.row.col.f16.f16.f16.f16 "
        "{%0,%1}, {%2,%3,%4,%5}, {%6,%7}, {%0,%1};"
        : "+r"(c[0]), "+r"(c[1])
        : "r"(a[0]), "r"(a[1]), "r"(a[2]), "r"(a[3]), "r"(b0), "r"(b1));
}
#define CP_ASYNC16(dst, src) \
    asm volatile("cp.async.ca.shared.global [%0], [%1], 16;" :: "r"(dst), "l"(src))
#define CP_COMMIT() asm volatile("cp.async.commit_group;")
#define CP_WAIT0()  asm volatile("cp.async.wait_group 0;")

__device__ __forceinline__ uint2 cvt4h(float4 v) {
    __half2 a = __floats2half2_rn(v.x, v.y);
    __half2 b = __floats2half2_rn(v.z, v.w);
    uint2 r;
    r.x = *reinterpret_cast<uint32_t*>(&a);
    r.y = *reinterpret_cast<uint32_t*>(&b);
    return r;
}

// ================= tensor-core batched GEMM =================
// 2-term fp16: Ph*Ahi (f32 acc) + Ph*Alo (f16 acc — small correction)
// Y[n][b][o] = sum_d P[n][o][d] * Act[(b*64+n)][d]
// CTA tile 128b x 128o x 64k; 8 warps (2b x 4o), warp tile 64x32.
// All launches use full tiles (no M predicates).
// smem buffer: AH 16K | AL 16K | PH 16K ; double buffered (96 KB).
#define GBUF 49152
#define GSMEM (2 * GBUF)

__global__ __launch_bounds__(256) void gemm_mma(
    const float* __restrict__ Pw,
    const __half* __restrict__ Ah, const __half* __restrict__ Al,
    float* __restrict__ Y, int K, int M, int relu, int stats)
{
    extern __shared__ char sm[];
    const int tid = threadIdx.x, wid = tid >> 5, lid = tid & 31;
    const int m0 = blockIdx.x * 128, b0 = blockIdx.y * 128, n = blockIdx.z;
    const int nchunk = K >> 6;
    uint32_t sb = smem_u32(sm);

    // global-load indexing
    const int r0 = tid >> 4, c4 = tid & 15;
    const int cswP = (((c4 >> 1) ^ (r0 & 7)) << 4) + (c4 & 1) * 8;
    const int ac = c4 & 7;
    const int aregion = (c4 < 8) ? 0 : 16384;
    const int cswA = ((ac ^ (r0 & 7)) << 4);
    const __half* Asrc = (c4 < 8) ? Ah : Al;

    // ldmatrix lane geometry
    const int lr  = (lid & 7) + ((lid >> 3) & 1) * 8;
    const int kch = lid >> 4;
    const int warp_b = wid >> 2, warp_o = wid & 3;
    int rowA128[4], r7A[4], rowB128[2], r7B[2];
#pragma unroll
    for (int mm = 0; mm < 4; mm++) {
        int r = warp_b * 64 + mm * 16 + lr;
        rowA128[mm] = r * 128; r7A[mm] = r & 7;
    }
#pragma unroll
    for (int g = 0; g < 2; g++) {
        int r = warp_o * 32 + g * 16 + lr;
        rowB128[g] = r * 128; r7B[g] = r & 7;
    }

    float acc[4][4][4];
    uint32_t acc16[4][4][2];
#pragma unroll
    for (int i = 0; i < 4; i++)
#pragma unroll
        for (int j = 0; j < 4; j++) {
#pragma unroll
            for (int q = 0; q < 4; q++) acc[i][j][q] = 0.f;
            acc16[i][j][0] = 0u; acc16[i][j][1] = 0u;
        }

    float4 stP[8];

    // ---- prologue: chunk 0 ----
#pragma unroll
    for (int j = 0; j < 8; j++) {
        int row = j * 16 + r0;
        const void* src = &Asrc[((size_t)(b0 + row) * 64 + n) * K + ac * 8];
        CP_ASYNC16(sb + aregion + row * 128 + cswA, src);
    }
    CP_COMMIT();
#pragma unroll
    for (int j = 0; j < 8; j++) {
        int row = j * 16 + r0;
        stP[j] = *(const float4*)&Pw[((size_t)n * M + m0 + row) * K + c4 * 4];
    }
#pragma unroll
    for (int j = 0; j < 8; j++) {
        int row = j * 16 + r0;
        *(uint2*)(sm + 32768 + row * 128 + cswP) = cvt4h(stP[j]);
    }
    CP_WAIT0();
    __syncthreads();

    for (int c = 0; c < nchunk; c++) {
        if (c + 1 < nchunk) {
            int k0 = (c + 1) << 6;
            uint32_t bdst = sb + ((c + 1) & 1) * GBUF;
#pragma unroll
            for (int j = 0; j < 8; j++) {
                int row = j * 16 + r0;
                const void* src = &Asrc[((size_t)(b0 + row) * 64 + n) * K + k0 + ac * 8];
                CP_ASYNC16(bdst + aregion + row * 128 + cswA, src);
            }
            CP_COMMIT();
#pragma unroll
            for (int j = 0; j < 8; j++) {
                int row = j * 16 + r0;
                stP[j] = *(const float4*)&Pw[((size_t)n * M + m0 + row) * K + k0 + c4 * 4];
            }
        }

        // ---- compute on buffer c&1 ----
        uint32_t ub = sb + (c & 1) * GBUF;
#pragma unroll
        for (int kk = 0; kk < 4; kk++) {
            uint32_t ah[4][4], al[4][4], bh[2][4];
            int ksel = kk * 2 + kch;
#pragma unroll
            for (int mm = 0; mm < 4; mm++)
                ldmx4(ah[mm], ub + rowA128[mm] + ((ksel ^ r7A[mm]) << 4));
#pragma unroll
            for (int mm = 0; mm < 4; mm++)
                ldmx4(al[mm], ub + 16384 + rowA128[mm] + ((ksel ^ r7A[mm]) << 4));
#pragma unroll
            for (int g = 0; g < 2; g++)
                ldmx4(bh[g], ub + 32768 + rowB128[g] + ((ksel ^ r7B[g]) << 4));
#pragma unroll
            for (int mm = 0; mm < 4; mm++)
#pragma unroll
                for (int nn = 0; nn < 4; nn++) {
                    int g = nn >> 1, s = nn & 1;
                    mma_f16(acc[mm][nn], ah[mm], bh[g][s], bh[g][s + 2]);
                    mma_f16acc(acc16[mm][nn], al[mm], bh[g][s], bh[g][s + 2]);
                }
        }

        if (c + 1 < nchunk) {
            char* buf = sm + ((c + 1) & 1) * GBUF;
#pragma unroll
            for (int j = 0; j < 8; j++) {
                int row = j * 16 + r0;
                *(uint2*)(buf + 32768 + row * 128 + cswP) = cvt4h(stP[j]);
            }
            CP_WAIT0();
        }
        __syncthreads();
    }

    // ---- merge f16 correction + relu ----
#pragma unroll
    for (int i = 0; i < 4; i++)
#pragma unroll
        for (int j = 0; j < 4; j++) {
            __half2 p0 = *reinterpret_cast<__half2*>(&acc16[i][j][0]);
            __half2 p1 = *reinterpret_cast<__half2*>(&acc16[i][j][1]);
            acc[i][j][0] += __low2float(p0);
            acc[i][j][1] += __high2float(p0);
            acc[i][j][2] += __low2float(p1);
            acc[i][j][3] += __high2float(p1);
        }
    if (relu) {
#pragma unroll
        for (int i = 0; i < 4; i++)
#pragma unroll
            for (int j = 0; j < 4; j++)
#pragma unroll
                for (int q = 0; q < 4; q++) acc[i][j][q] = fmaxf(acc[i][j][q], 0.f);
    }

#pragma unroll
    for (int mm = 0; mm < 4; mm++) {
        int bg = b0 + warp_b * 64 + mm * 16 + (lid >> 2);
#pragma unroll
        for (int nn = 0; nn < 4; nn++) {
            int og = m0 + warp_o * 32 + nn * 8 + (lid & 3) * 2;
            float2 v01 = make_float2(acc[mm][nn][0], acc[mm][nn][1]);
            float2 v23 = make_float2(acc[mm][nn][2], acc[mm][nn][3]);
            *(float2*)&Y[((size_t)n * 256 + bg) * M + og] = v01;
            *(float2*)&Y[((size_t)n * 256 + bg + 8) * M + og] = v23;
        }
    }

    // fused BN partial stats (deterministic per-slot, no atomics)
    if (stats) {
        float s1[8], s2v[8];
#pragma unroll
        for (int k = 0; k < 8; k++) { s1[k] = 0.f; s2v[k] = 0.f; }
#pragma unroll
        for (int nn = 0; nn < 4; nn++)
#pragma unroll
            for (int q = 0; q < 2; q++) {
                int k = nn * 2 + q;
#pragma unroll
                for (int mm = 0; mm < 4; mm++) {
                    float v0 = acc[mm][nn][q], v1 = acc[mm][nn][q + 2];
                    s1[k] += v0 + v1;
                    s2v[k] += v0 * v0 + v1 * v1;
                }
            }
#pragma unroll
        for (int k = 0; k < 8; k++)
#pragma unroll
            for (int msk = 4; msk <= 16; msk <<= 1) {
                s1[k]  += __shfl_xor_sync(0xFFFFFFFFu, s1[k],  msk);
                s2v[k] += __shfl_xor_sync(0xFFFFFFFFu, s2v[k], msk);
            }
        if ((lid >> 2) == 0) {
            int slot = (blockIdx.y * 64 + blockIdx.z) * 2 + warp_b;
#pragma unroll
            for (int nn = 0; nn < 4; nn++)
#pragma unroll
                for (int q = 0; q < 2; q++) {
                    int ch = m0 + warp_o * 32 + nn * 8 + (lid & 3) * 2 + q;
                    g_pS [slot * CDIM + ch] = s1[nn * 2 + q];
                    g_pS2[slot * CDIM + ch] = s2v[nn * 2 + q];
                }
        }
    }
}

// ================= pre/post kernels =================
__global__ void build_a0(const float* __restrict__ Hre, const float* __restrict__ Him) {
    int b = blockIdx.x, t = threadIdx.x;
    const float* hr = Hre + (size_t)b * 2048;
    const float* hi = Him + (size_t)b * 2048;
    size_t dbase = (size_t)b * 4096;
#pragma unroll
    for (int j = 0; j < 8; j++) {
        int idx = t + j * 256;
        int n = idx >> 5, d = idx & 31;
        float v0 = hr[idx], v1 = hi[idx];
        __half h0 = __float2half_rn(v0);
        __half h1 = __float2half_rn(v1);
        g_A0h[dbase + n * 64 + d]      = h0;
        g_A0h[dbase + n * 64 + 32 + d] = h1;
        g_A0l[dbase + n * 64 + d]      = __float2half_rn(v0 - __half2float(h0));
        g_A0l[dbase + n * 64 + 32 + d] = __float2half_rn(v1 - __half2float(h1));
    }
}

// slot-parallel BN finalize: 32 blocks x 256 thr
__global__ void bn_finalize(const float* __restrict__ w, const float* __restrict__ bb) {
    int c = blockIdx.x * 32 + (threadIdx.x & 31);
    int g = threadIdx.x >> 5;   // 0..7
    float s = 0.f, s2 = 0.f;
#pragma unroll
    for (int i = 0; i < 32; i++) {
        int sl = g * 32 + i;
        s  += g_pS [sl * CDIM + c];
        s2 += g_pS2[sl * CDIM + c];
    }
    __shared__ float a1[8][32], a2[8][32];
    a1[g][threadIdx.x & 31] = s;
    a2[g][threadIdx.x & 31] = s2;
    __syncthreads();
    if (g == 0) {
        float ts = 0.f, ts2 = 0.f;
#pragma unroll
        for (int j = 0; j < 8; j++) { ts += a1[j][threadIdx.x & 31]; ts2 += a2[j][threadIdx.x & 31]; }
        float mean = ts / (float)BL;
        float var  = ts2 / (float)BL - mean * mean;
        float sc = w[c] * rsqrtf(var + 1e-5f);
        g_scale[c] = sc;
        g_shift[c] = bb[c] - mean * sc;
    }
}

// fused BN-apply + softplus + closed-form noise MI; vectorized float4, 128 thr/blk
__global__ void bn_noise(const float* __restrict__ Y, const float* __restrict__ Nz, int add) {
    int nb = blockIdx.x, t = threadIdx.x;
    int n = nb >> 8, b = nb & 255;
    size_t ybase = (size_t)nb * CDIM;
    size_t bl = (size_t)b * 64 + n;
    size_t mbase = bl * HDIM;
    int d = t * 4;

    float4 ym = *(const float4*)&Y[ybase + d];
    float4 ys = *(const float4*)&Y[ybase + HDIM + d];
    float4 scm = *(const float4*)&g_scale[d];
    float4 shm = *(const float4*)&g_shift[d];
    float4 scs = *(const float4*)&g_scale[HDIM + d];
    float4 shs = *(const float4*)&g_shift[HDIM + d];
    float4 n0 = *(const float4*)&Nz[mbase + d];
    float4 n1 = *(const float4*)&Nz[mbase + d + NS_STRIDE];
    float4 n2 = *(const float4*)&Nz[mbase + d + 2 * NS_STRIDE];
    float4 n3 = *(const float4*)&Nz[mbase + d + 3 * NS_STRIDE];

    float m[4] = { scm.x * ym.x + shm.x, scm.y * ym.y + shm.y,
                   scm.z * ym.z + shm.z, scm.w * ym.w + shm.w };
    float x[4] = { scs.x * ys.x + shs.x, scs.y * ys.y + shs.y,
                   scs.z * ys.z + shs.z, scs.w * ys.w + shs.w };
    float nn0[4] = { n0.x, n0.y, n0.z, n0.w };
    float nn1[4] = { n1.x, n1.y, n1.z, n1.w };
    float nn2[4] = { n2.x, n2.y, n2.z, n2.w };
    float nn3[4] = { n3.x, n3.y, n3.z, n3.w };

    float local = 0.f;
    float lo[4];
#pragma unroll
    for (int i = 0; i < 4; i++) {
        float s = fmaxf(x[i], 0.f) + log1pf(__expf(-fabsf(x[i]))) + 1e-10f;
        float S1 = (nn0[i] + nn1[i] + nn2[i] + nn3[i]) * 0.25f;
        float S2 = (nn0[i] * nn0[i] + nn1[i] * nn1[i] +
                    nn2[i] * nn2[i] + nn3[i] * nn3[i]) * 0.25f;
        local += 0.5f * m[i] * m[i] - __logf(s) + m[i] * s * S1
               + 0.5f * (s * s - 1.0f) * S2;
        __half mh = __float2half_rn(m[i]);
        lo[i] = m[i] - __half2float(mh);
        m[i] = __half2float(mh);
    }
    __half2 mh01 = __floats2half2_rn(m[0], m[1]);
    __half2 mh23 = __floats2half2_rn(m[2], m[3]);
    __half2 ml01 = __floats2half2_rn(lo[0], lo[1]);
    __half2 ml23 = __floats2half2_rn(lo[2], lo[3]);
    uint2 hv, lv;
    hv.x = *reinterpret_cast<uint32_t*>(&mh01);
    hv.y = *reinterpret_cast<uint32_t*>(&mh23);
    lv.x = *reinterpret_cast<uint32_t*>(&ml01);
    lv.y = *reinterpret_cast<uint32_t*>(&ml23);
    *(uint2*)&g_Mh[mbase + d] = hv;
    *(uint2*)&g_Ml[mbase + d] = lv;

    __shared__ float sh[128];
    sh[t] = local;
    __syncthreads();
    for (int off = 64; off; off >>= 1) {
        if (t < off) sh[t] += sh[t + off];
        __syncthreads();
    }
    if (t == 0) {
        if (add) g_Ipart[bl] += sh[0];
        else     g_Ipart[bl]  = sh[0];
    }
}

// merged pn + final + I-sum: one block per b (256 blocks, 128 threads)
__global__ void epilogue_kernel(float* __restrict__ out) {
    int b = blockIdx.x, t = threadIdx.x;
    __shared__ float v[64][72];
    __shared__ float pk[64];
    __shared__ float Pn[8];
    __shared__ float mult[64][8];

    for (int idx = t; idx < 64 * 72; idx += 128) {
        int n = idx / 72, c = idx % 72;
        v[n][c] = g_Y2[((size_t)(n * 256 + b)) * MOUT + c];
    }
    __syncthreads();
    if (t < 64) {
        int k = t & 7, j = t >> 3;
        float s = 0.f;
#pragma unroll
        for (int n = j; n < 64; n += 8) { float x = v[n][64 + k]; s += x * x; }
        pk[t] = s;
    }
    __syncthreads();
    if (t < 8) {
        float tot = 0.f;
#pragma unroll
        for (int j = 0; j < 8; j++) tot += pk[j * 8 + t];
        Pn[t] = sqrtf(tot);
    }
    __syncthreads();
    for (int idx = t; idx < 512; idx += 128) {
        int n = idx >> 3, k = idx & 7;
        float ss = 0.f;
#pragma unroll
        for (int u = 0; u < 4; u++) {
            float a = v[n][k * 4 + u], c2 = v[n][32 + k * 4 + u];
            ss += a * a + c2 * c2;
        }
        mult[n][k] = v[n][64 + k] / Pn[k] * 8.0f / sqrtf(ss);  // sqrt(L)=8
    }
    __syncthreads();
    for (int idx = t; idx < 64 * 32; idx += 128) {
        int n = idx >> 5, c = idx & 31;
        size_t obase = ((size_t)b * 64 + n) * 32;
        float mlt = mult[n][c >> 2];
        out[OUT_FRE + obase + c] = v[n][c] * mlt;
        out[OUT_FIM + obase + c] = v[n][32 + c] * mlt;
    }
    if (t < 64) pk[t] = g_Ipart[(size_t)b * 64 + t];
    __syncthreads();
    if (t == 0) {
        float s = 0.f;
#pragma unroll
        for (int n = 0; n < 64; n++) s += pk[n];
        out[OUT_I + b] = s;
    }
}

// ================= launch =================
extern "C" void kernel_launch(void* const* d_in, const int* in_sizes, int n_in,
                              void* d_out, int out_size) {
    const float* Hre = (const float*)d_in[0];
    const float* Him = (const float*)d_in[1];
    const float* P0  = (const float*)d_in[2];
    const float* P1  = (const float*)d_in[3];
    const float* P2  = (const float*)d_in[4];
    const float* w0  = (const float*)d_in[5];
    const float* b0  = (const float*)d_in[6];
    const float* w1  = (const float*)d_in[7];
    const float* b1  = (const float*)d_in[8];
    const float* nz0 = (const float*)d_in[9];
    const float* nz1 = (const float*)d_in[10];
    float* out = (float*)d_out;

    float *Yp, *Y2p;
    __half *A0h, *A0l, *Mh, *Ml;
    cudaGetSymbolAddress((void**)&A0h, g_A0h);
    cudaGetSymbolAddress((void**)&A0l, g_A0l);
    cudaGetSymbolAddress((void**)&Yp,  g_Y);
    cudaGetSymbolAddress((void**)&Mh,  g_Mh);
    cudaGetSymbolAddress((void**)&Ml,  g_Ml);
    cudaGetSymbolAddress((void**)&Y2p, g_Y2);

    cudaFuncSetAttribute(gemm_mma, cudaFuncAttributeMaxDynamicSharedMemorySize, GSMEM);

    // layer 0: K=64
    build_a0<<<BDIM, 256>>>(Hre, Him);
    gemm_mma<<<dim3(8, 2, 64), 256, GSMEM>>>(P0, A0h, A0l, Yp, DIN, CDIM, 1, 1);
    bn_finalize<<<32, 256>>>(w0, b0);
    bn_noise<<<BL, 128>>>(Yp, nz0, 0);

    // layer 1: K=512
    gemm_mma<<<dim3(8, 2, 64), 256, GSMEM>>>(P1, Mh, Ml, Yp, HDIM, CDIM, 1, 1);
    bn_finalize<<<32, 256>>>(w1, b1);
    bn_noise<<<BL, 128>>>(Yp, nz1, 1);

    // layer 2: K=512 — only channels 0..127 are ever read (epilogue uses c<72)
    gemm_mma<<<dim3(1, 2, 64), 256, GSMEM>>>(P2, Mh, Ml, Y2p, HDIM, MOUT, 0, 0);

    // merged epilogue
    epilogue_kernel<<<BDIM, 128>>>(out);
}